// round 15
// baseline (speedup 1.0000x reference)
#include <cuda_runtime.h>

#define BATCH 256
#define D0    1024
#define DH    2048
#define DL    10
#define TSTEPS 64

#define BM 64
#define BN 64
#define BK 16
#define TM 4
#define TN 8
#define NTHREADS 128

typedef long long ll;

// ------------------------- buffer layout (elements) -------------------------
constexpr ll SZ_B0 = (ll)BATCH * D0;
constexpr ll SZ_BH = (ll)BATCH * DH;
constexpr ll SZ_BL = (ll)BATCH * DL;

constexpr ll O_W0T = 0;                          // [DH][D0]  (W0 is [D0][DH])
constexpr ll O_W1T = O_W0T + (ll)D0 * DH;        // [DH][DH]
constexpr ll O_W2T = O_W1T + (ll)DH * DH;
constexpr ll O_V0T = O_W2T + (ll)DH * DH;        // [D0][DH]  (V0 is [DH][D0])
constexpr ll O_V1T = O_V0T + (ll)D0 * DH;        // [DH][DH]
constexpr ll O_V2T = O_V1T + (ll)DH * DH;
constexpr ll O_XDV = O_V2T + (ll)DH * DH;        // x_data @ V0^T  [B,DH]
constexpr ll O_YW3 = O_XDV + SZ_BH;              // y @ W3^T       [B,DH]
constexpr ll O_P1  = O_YW3 + SZ_BH;              // partial (-ed-eg)+G1, layer 1..3
constexpr ll O_P2  = O_P1 + SZ_BH;
constexpr ll O_P3  = O_P2 + SZ_BH;
constexpr ll O_STATE = O_P3 + SZ_BH;
constexpr ll O_V0L  = O_STATE;
constexpr ll O_J0   = O_V0L + SZ_B0;
constexpr ll O_EG0A = O_J0  + SZ_B0;
constexpr ll O_EG0B = O_EG0A + SZ_B0;
constexpr ll O_V1   = O_EG0B + SZ_B0;
constexpr ll O_J1   = O_V1 + SZ_BH;
constexpr ll O_X1   = O_J1 + SZ_BH;
constexpr ll O_S1A  = O_X1 + SZ_BH;
constexpr ll O_S1B  = O_S1A + SZ_BH;
constexpr ll O_V2   = O_S1B + SZ_BH;
constexpr ll O_J2   = O_V2 + SZ_BH;
constexpr ll O_X2   = O_J2 + SZ_BH;
constexpr ll O_S2   = O_X2 + SZ_BH;
constexpr ll O_V3L  = O_S2 + SZ_BH;
constexpr ll O_J3   = O_V3L + SZ_BH;
constexpr ll O_X3   = O_J3 + SZ_BH;
constexpr ll O_S3   = O_X3 + SZ_BH;
constexpr ll O_EG1  = O_S3 + SZ_BH;
constexpr ll O_EG2  = O_EG1 + SZ_BH;
constexpr ll O_EG3  = O_EG2 + SZ_BH;
constexpr ll O_ED1  = O_EG3 + SZ_BH;
constexpr ll O_ED2  = O_ED1 + SZ_BH;
constexpr ll O_ED3  = O_ED2 + SZ_BH;
constexpr ll O_V4   = O_ED3 + SZ_BH;
constexpr ll O_J4   = O_V4 + SZ_BL;
constexpr ll O_ED4  = O_J4 + SZ_BL;
constexpr ll O_SC   = O_ED4 + SZ_BL;
constexpr ll O_VS   = O_SC + SZ_BL;
constexpr ll O_END  = O_VS + SZ_BL;

__device__ float g_buf[O_END];

// Exact-rounded LIF matching XLA's separate mul/add roundings (no FMA contraction).
__device__ __forceinline__ void lif_ref(float inp, float& v, float& jm, float& s) {
    jm = __fadd_rn(jm, __fmul_rn(0.1f,  __fadd_rn(inp, -jm)));   // j += 0.1*(-j+inp)
    v  = __fadd_rn(v,  __fmul_rn(0.05f, __fadd_rn(jm, -v)));     // v += 0.05*(-v+j)
    bool sp = (v > 1.0f);
    s = sp ? 1.0f : 0.0f;
    v = sp ? 0.0f : v;
}

// ------------------------------ descriptors --------------------------------
struct GDesc {
    const float* A; const float* B; int K; int N; int mode;
    // mode 11: e_out = G
    // mode 12: e_out = ((-bias1) + (-bias2)) + G
    // mode  0: layer0 LIF: inp=G; e_out = 0.5*(e_ref - s)
    // mode  1: hidden LIF: inp = bias1 + G; trace; optional e_out = 0.5*(x - e_ref)
    // mode 10: e_out = 0.5*(e_ref - G)
    float* v; float* jm; float* sp; float* xt;
    const float* bias1; const float* bias2;
    float* e_out; const float* e_ref;
};
struct GDescs4 { GDesc d[4]; };

// ------------------------------ fused GEMM ---------------------------------
// C[256,N] = A[256,K] @ B[K,N]; per-output strictly-ascending-k FFMA chain.
// BM=64 x BN=64 tile, 128 threads, TM=4 x TN=8 per thread (32 accs) -> ~80 regs,
// 4 blocks/SM co-resident (16 warps/SM) for latency hiding.
__global__ void __launch_bounds__(NTHREADS, 4)
fused_gemm(GDescs4 descs) {
    const GDesc d = descs.d[blockIdx.z];
    if ((int)blockIdx.y * BN >= d.N) return;

    __shared__ float As[2][BK][BM + 4];
    __shared__ float Bs[2][BK][BN];

    const int tid = threadIdx.x;
    const int tx = tid & 7;        // 8 col-groups * TN=8 -> 64 cols
    const int ty = tid >> 3;       // 16 row-groups * TM=4 -> 64 rows
    const int m0 = blockIdx.x * BM;
    const int n0 = blockIdx.y * BN;

    float acc[TM][TN];
#pragma unroll
    for (int i = 0; i < TM; i++)
#pragma unroll
        for (int j = 0; j < TN; j++) acc[i][j] = 0.f;

    const int total = (d.K + BK - 1) / BK;

    float aReg[8];                 // 64*16/128 = 8 A elems per thread
    float4 bReg[2];                // 16*64/128 = 8 B elems = 2 float4

    auto g2r = [&](int t) {
        const int k0 = t * BK;
#pragma unroll
        for (int i = 0; i < 8; i++) {
            int e = tid + i * NTHREADS;       // 64*16 = 1024 elems
            int m = e >> 4, k = e & 15;
            int kg = k0 + k;
            aReg[i] = (kg < d.K) ? d.A[(m0 + m) * d.K + kg] : 0.f;
        }
#pragma unroll
        for (int i = 0; i < 2; i++) {
            int ef = tid + i * NTHREADS;      // 16 rows x 16 float4
            int r = ef >> 4, c4 = ef & 15;
            int kg = k0 + r;
            bReg[i] = (kg < d.K) ? *(const float4*)(d.B + (ll)kg * d.N + n0 + c4 * 4)
                                 : make_float4(0.f, 0.f, 0.f, 0.f);
        }
    };
    auto r2s = [&](int buf) {
#pragma unroll
        for (int i = 0; i < 8; i++) {
            int e = tid + i * NTHREADS;
            As[buf][e & 15][e >> 4] = aReg[i];
        }
#pragma unroll
        for (int i = 0; i < 2; i++) {
            int ef = tid + i * NTHREADS;
            *(float4*)&Bs[buf][ef >> 4][(ef & 15) * 4] = bReg[i];
        }
    };

    g2r(0); r2s(0); __syncthreads();

    for (int t = 0; t < total; ++t) {
        const int cur = t & 1;
        if (t + 1 < total) g2r(t + 1);
#pragma unroll
        for (int k = 0; k < BK; k++) {       // ascending k: single FFMA chain per output
            float a[TM], b[TN];
            *(float4*)&a[0] = *(const float4*)&As[cur][k][ty * TM];
            *(float4*)&b[0] = *(const float4*)&Bs[cur][k][tx * TN];
            *(float4*)&b[4] = *(const float4*)&Bs[cur][k][tx * TN + 4];
#pragma unroll
            for (int i = 0; i < TM; i++)
#pragma unroll
                for (int j = 0; j < TN; j++)
                    acc[i][j] += a[i] * b[j];   // FFMA (zero-padded terms exact no-ops)
        }
        if (t + 1 < total) r2s(cur ^ 1);
        __syncthreads();
    }

    // epilogue — exact separate-rounded ops in reference order
#pragma unroll
    for (int i = 0; i < TM; i++) {
        const int row = m0 + ty * TM + i;
#pragma unroll
        for (int j = 0; j < TN; j++) {
            const int col = n0 + tx * TN + j;
            const int idx = row * d.N + col;
            float G = acc[i][j];
            if (d.mode == 11) { d.e_out[idx] = G; continue; }
            if (d.mode == 12) {
                float t0 = __fadd_rn(-d.bias1[idx], -d.bias2[idx]);  // (-ed) + (-eg)
                d.e_out[idx] = __fadd_rn(t0, G);                     // (..) + G1
                continue;
            }
            if (d.mode == 10) {
                d.e_out[idx] = __fmul_rn(0.5f, __fsub_rn(d.e_ref[idx], G));
                continue;
            }
            float inp = (d.mode == 0) ? G : __fadd_rn(d.bias1[idx], G);  // P + G2
            float jm = d.jm[idx], v = d.v[idx], s;
            lif_ref(inp, v, jm, s);
            d.jm[idx] = jm; d.v[idx] = v;
            if (d.mode == 0) {
                d.e_out[idx] = __fmul_rn(0.5f, __fsub_rn(d.e_ref[idx], s));  // eg0
            } else {
                d.sp[idx] = s;
                float x = d.xt[idx];
                float q = __fdiv_rn(x, 20.0f);
                x = __fadd_rn(x, __fadd_rn(s, -q));   // x + ((-x/20) + s)
                d.xt[idx] = x;
                if (d.e_out)
                    d.e_out[idx] = __fmul_rn(0.5f, __fsub_rn(x, d.e_ref[idx]));
            }
        }
    }
}

// --------- label layer: one thread per output, ascending-k FMA chain --------
__global__ void label_k(const float* __restrict__ s3, const float* __restrict__ V3,
                        const float* __restrict__ y,
                        float* v4, float* j4, float* ed4, float* sc, float* vs) {
    int idx = blockIdx.x * blockDim.x + threadIdx.x;    // BATCH*DL = 2560
    if (idx >= BATCH * DL) return;
    int b = idx / DL, n = idx % DL;
    const float* srow = s3 + (ll)b * DH;
    const float* vrow = V3 + (ll)n * DH;                // V3 [DL][DH]: row n
    float acc = 0.f;
    for (int k = 0; k < DH; k++)
        acc += srow[k] * vrow[k];                       // single FFMA chain
    float jm = j4[idx], v = v4[idx], s;
    lif_ref(acc, v, jm, s);
    j4[idx] = jm; v4[idx] = v;
    ed4[idx] = __fmul_rn(0.5f, __fsub_rn(y[idx], s));
    sc[idx] = __fadd_rn(sc[idx], s);
    vs[idx] = __fadd_rn(vs[idx], v);
}

// ------------------------------ helpers ------------------------------------
struct TDesc { const float* src; float* dst; int rows, cols; };
struct TDescs { TDesc d[6]; };

__global__ void transpose_k(TDescs ds) {
    TDesc d = ds.d[blockIdx.z];
    const int c0 = blockIdx.x * 32, r0 = blockIdx.y * 32;
    if (c0 >= d.cols || r0 >= d.rows) return;
    __shared__ float tile[32][33];
    const int tx = threadIdx.x, ty = threadIdx.y;   // 32x8
    for (int i = ty; i < 32; i += 8) {
        int r = r0 + i, c = c0 + tx;
        tile[i][tx] = (r < d.rows && c < d.cols) ? d.src[(ll)r * d.cols + c] : 0.f;
    }
    __syncthreads();
    for (int i = ty; i < 32; i += 8) {
        int c = c0 + i, r = r0 + tx;
        if (c < d.cols && r < d.rows) d.dst[(ll)c * d.rows + r] = tile[tx][i];
    }
}

__global__ void ygemm_k(const float* __restrict__ y, const float* __restrict__ W3,
                        float* __restrict__ out) {
    int idx = blockIdx.x * blockDim.x + threadIdx.x;     // BATCH*DH
    if (idx >= BATCH * DH) return;
    int b = idx / DH, n = idx % DH;
    float acc = 0.f;
#pragma unroll
    for (int k = 0; k < DL; k++)
        acc += y[b * DL + k] * W3[(ll)n * DL + k];       // ascending FFMA chain
    out[idx] = acc;
}

__global__ void zero_k(float* p, ll n) {
    ll i = (ll)blockIdx.x * blockDim.x + threadIdx.x;
    if (i < n) p[i] = 0.f;
}

__global__ void writeout_k(const float* sc, const float* vs, float* out) {
    int i = blockIdx.x * blockDim.x + threadIdx.x;
    if (i < BATCH * DL) out[i] = sc[i];
    else if (i < 2 * BATCH * DL) out[i] = vs[i - BATCH * DL];
}

// ------------------------------ host side ----------------------------------
static inline GDesc mk(const float* A, const float* B, int K, int N, int mode,
                       float* v, float* jm, float* sp, float* xt,
                       const float* b1, const float* b2,
                       float* e_out, const float* e_ref) {
    GDesc g; g.A = A; g.B = B; g.K = K; g.N = N; g.mode = mode;
    g.v = v; g.jm = jm; g.sp = sp; g.xt = xt;
    g.bias1 = b1; g.bias2 = b2; g.e_out = e_out; g.e_ref = e_ref;
    return g;
}

extern "C" void kernel_launch(void* const* d_in, const int* in_sizes, int n_in,
                              void* d_out, int out_size) {
    // metadata order = setup_inputs() dict insertion order (interleaved W/V):
    const float* x_data = (const float*)d_in[0];
    const float* y_t    = (const float*)d_in[1];
    const float* W0 = (const float*)d_in[2];   // [1024][2048]
    const float* V0 = (const float*)d_in[3];   // [2048][1024]
    const float* W1 = (const float*)d_in[4];   // [2048][2048]
    const float* V1 = (const float*)d_in[5];   // [2048][2048]
    const float* W2 = (const float*)d_in[6];   // [2048][2048]
    const float* V2 = (const float*)d_in[7];   // [2048][2048]
    const float* W3 = (const float*)d_in[8];   // [2048][10]
    const float* V3 = (const float*)d_in[9];   // [10][2048]
    float* out = (float*)d_out;

    float* buf = nullptr;
    cudaGetSymbolAddress((void**)&buf, g_buf);

    // zero mutable state
    {
        ll nz = O_END - O_STATE;
        zero_k<<<(unsigned)((nz + 255) / 256), 256>>>(buf + O_STATE, nz);
    }

    // one-time weight transposes
    {
        TDescs td;
        td.d[0] = { W0, buf + O_W0T, D0, DH };
        td.d[1] = { W1, buf + O_W1T, DH, DH };
        td.d[2] = { W2, buf + O_W2T, DH, DH };
        td.d[3] = { V0, buf + O_V0T, DH, D0 };
        td.d[4] = { V1, buf + O_V1T, DH, DH };
        td.d[5] = { V2, buf + O_V2T, DH, DH };
        transpose_k<<<dim3(64, 64, 6), dim3(32, 8)>>>(td);
    }

    // loop-invariant GEMMs
    ygemm_k<<<(BATCH * DH + 255) / 256, 256>>>(y_t, W3, buf + O_YW3);
    {
        GDescs4 g;
        g.d[0] = mk(x_data, buf + O_V0T, D0, DH, 11,
                    nullptr, nullptr, nullptr, nullptr, nullptr, nullptr,
                    buf + O_XDV, nullptr);
        g.d[1] = g.d[0]; g.d[2] = g.d[0]; g.d[3] = g.d[0];
        fused_gemm<<<dim3(BATCH / BM, 32, 1), NTHREADS>>>(g);
    }

    for (int t = 0; t < TSTEPS; ++t) {
        const int cur = t & 1;
        float* eg0c = buf + (cur ? O_EG0B : O_EG0A);
        float* eg0p = buf + (cur ? O_EG0A : O_EG0B);
        float* s1c  = buf + (cur ? O_S1B : O_S1A);
        float* s1p  = buf + (cur ? O_S1A : O_S1B);

        // ---- update pass 1: layer0 LIF + partials P_i = (-ed_i - eg_i) + G1_i ----
        GDescs4 u1;
        u1.d[0] = mk(s1p, buf + O_W0T, DH, D0, 0,
                     buf + O_V0L, buf + O_J0, nullptr, nullptr,
                     nullptr, nullptr, eg0c, x_data);
        u1.d[1] = mk(eg0p, W0, D0, DH, 12,
                     nullptr, nullptr, nullptr, nullptr,
                     buf + O_ED1, buf + O_EG1, buf + O_P1, nullptr);
        u1.d[2] = mk(buf + O_EG1, W1, DH, DH, 12,
                     nullptr, nullptr, nullptr, nullptr,
                     buf + O_ED2, buf + O_EG2, buf + O_P2, nullptr);
        u1.d[3] = mk(buf + O_EG2, W2, DH, DH, 12,
                     nullptr, nullptr, nullptr, nullptr,
                     buf + O_ED3, buf + O_EG3, buf + O_P3, nullptr);
        fused_gemm<<<dim3(BATCH / BM, 32, 4), NTHREADS>>>(u1);

        // ---- update pass 2: inp_i = P_i + G2_i, LIF + trace (+ fused ed1/eg3) ----
        GDescs4 u2;
        u2.d[0] = mk(buf + O_ED2, V1, DH, DH, 1,
                     buf + O_V1, buf + O_J1, s1c, buf + O_X1,
                     buf + O_P1, nullptr, buf + O_ED1, buf + O_XDV);
        u2.d[1] = mk(buf + O_ED3, V2, DH, DH, 1,
                     buf + O_V2, buf + O_J2, buf + O_S2, buf + O_X2,
                     buf + O_P2, nullptr, nullptr, nullptr);
        u2.d[2] = mk(buf + O_ED4, V3, DL, DH, 1,
                     buf + O_V3L, buf + O_J3, buf + O_S3, buf + O_X3,
                     buf + O_P3, nullptr, buf + O_EG3, buf + O_YW3);
        u2.d[3] = u2.d[2];   // unused (grid.z = 3)
        fused_gemm<<<dim3(BATCH / BM, 32, 3), NTHREADS>>>(u2);

        // ---- label layer (fresh s3) + readout accumulation ----
        label_k<<<(BATCH * DL + 255) / 256, 256>>>(buf + O_S3, V3, y_t,
                                                   buf + O_V4, buf + O_J4, buf + O_ED4,
                                                   buf + O_SC, buf + O_VS);

        // ---- error phase: 4 single-chain GEMMs ----
        GDescs4 e;
        e.d[0] = mk(buf + O_S2, buf + O_W1T, DH, DH, 10,
                    nullptr, nullptr, nullptr, nullptr, nullptr, nullptr,
                    buf + O_EG1, buf + O_X1);   // eg1 = .5(x1 - s2@W1^T)
        e.d[1] = mk(s1c, buf + O_V1T, DH, DH, 10,
                    nullptr, nullptr, nullptr, nullptr, nullptr, nullptr,
                    buf + O_ED2, buf + O_X2);   // ed2 = .5(x2 - s1@V1^T)
        e.d[2] = mk(buf + O_S3, buf + O_W2T, DH, DH, 10,
                    nullptr, nullptr, nullptr, nullptr, nullptr, nullptr,
                    buf + O_EG2, buf + O_X2);   // eg2 = .5(x2 - s3@W2^T)
        e.d[3] = mk(buf + O_S2, buf + O_V2T, DH, DH, 10,
                    nullptr, nullptr, nullptr, nullptr, nullptr, nullptr,
                    buf + O_ED3, buf + O_X3);   // ed3 = .5(x3 - s2@V2^T)
        fused_gemm<<<dim3(BATCH / BM, 32, 4), NTHREADS>>>(e);
    }

    writeout_k<<<(2 * BATCH * DL + 255) / 256, 256>>>(buf + O_SC, buf + O_VS, out);
}

// round 16
// speedup vs baseline: 1.2755x; 1.2755x over previous
#include <cuda_runtime.h>

#define BATCH 256
#define D0    1024
#define DH    2048
#define DL    10
#define TSTEPS 64

#define BM 128
#define BN 64
#define BK 16
#define TM 8
#define TN 4
#define NTHREADS 256

typedef long long ll;

// ------------------------- buffer layout (elements) -------------------------
constexpr ll SZ_B0 = (ll)BATCH * D0;
constexpr ll SZ_BH = (ll)BATCH * DH;
constexpr ll SZ_BL = (ll)BATCH * DL;

constexpr ll O_W0T = 0;                          // [DH][D0]  (W0 is [D0][DH])
constexpr ll O_W1T = O_W0T + (ll)D0 * DH;        // [DH][DH]
constexpr ll O_W2T = O_W1T + (ll)DH * DH;
constexpr ll O_V0T = O_W2T + (ll)DH * DH;        // [D0][DH]  (V0 is [DH][D0])
constexpr ll O_V1T = O_V0T + (ll)D0 * DH;        // [DH][DH]
constexpr ll O_V2T = O_V1T + (ll)DH * DH;
constexpr ll O_XDV = O_V2T + (ll)DH * DH;        // x_data @ V0^T  [B,DH]
constexpr ll O_YW3 = O_XDV + SZ_BH;              // y @ W3^T       [B,DH]
constexpr ll O_P1  = O_YW3 + SZ_BH;              // partial (-ed-eg)+G1, layer 1..3
constexpr ll O_P2  = O_P1 + SZ_BH;
constexpr ll O_P3  = O_P2 + SZ_BH;
constexpr ll O_STATE = O_P3 + SZ_BH;
constexpr ll O_V0L  = O_STATE;
constexpr ll O_J0   = O_V0L + SZ_B0;
constexpr ll O_EG0A = O_J0  + SZ_B0;
constexpr ll O_EG0B = O_EG0A + SZ_B0;
constexpr ll O_V1   = O_EG0B + SZ_B0;
constexpr ll O_J1   = O_V1 + SZ_BH;
constexpr ll O_X1   = O_J1 + SZ_BH;
constexpr ll O_S1A  = O_X1 + SZ_BH;
constexpr ll O_S1B  = O_S1A + SZ_BH;
constexpr ll O_V2   = O_S1B + SZ_BH;
constexpr ll O_J2   = O_V2 + SZ_BH;
constexpr ll O_X2   = O_J2 + SZ_BH;
constexpr ll O_S2   = O_X2 + SZ_BH;
constexpr ll O_V3L  = O_S2 + SZ_BH;
constexpr ll O_J3   = O_V3L + SZ_BH;
constexpr ll O_X3   = O_J3 + SZ_BH;
constexpr ll O_S3   = O_X3 + SZ_BH;
constexpr ll O_EG1  = O_S3 + SZ_BH;
constexpr ll O_EG2  = O_EG1 + SZ_BH;
constexpr ll O_EG3  = O_EG2 + SZ_BH;
constexpr ll O_ED1  = O_EG3 + SZ_BH;
constexpr ll O_ED2  = O_ED1 + SZ_BH;
constexpr ll O_ED3  = O_ED2 + SZ_BH;
constexpr ll O_V4   = O_ED3 + SZ_BH;
constexpr ll O_J4   = O_V4 + SZ_BL;
constexpr ll O_ED4  = O_J4 + SZ_BL;
constexpr ll O_SC   = O_ED4 + SZ_BL;
constexpr ll O_VS   = O_SC + SZ_BL;
constexpr ll O_END  = O_VS + SZ_BL;

__device__ float g_buf[O_END];

// Exact-rounded LIF matching XLA's separate mul/add roundings (no FMA contraction).
__device__ __forceinline__ void lif_ref(float inp, float& v, float& jm, float& s) {
    jm = __fadd_rn(jm, __fmul_rn(0.1f,  __fadd_rn(inp, -jm)));   // j += 0.1*(-j+inp)
    v  = __fadd_rn(v,  __fmul_rn(0.05f, __fadd_rn(jm, -v)));     // v += 0.05*(-v+j)
    bool sp = (v > 1.0f);
    s = sp ? 1.0f : 0.0f;
    v = sp ? 0.0f : v;
}

// ------------------------------ descriptors --------------------------------
struct GDesc {
    const float* A; const float* B; int K; int N; int mode;
    // mode 11: e_out = G
    // mode 12: e_out = ((-bias1) + (-bias2)) + G
    // mode  0: layer0 LIF: inp=G; e_out = 0.5*(e_ref - s)
    // mode  1: hidden LIF: inp = bias1 + G; trace; optional e_out = 0.5*(x - e_ref)
    // mode 10: e_out = 0.5*(e_ref - G)
    float* v; float* jm; float* sp; float* xt;
    const float* bias1; const float* bias2;
    float* e_out; const float* e_ref;
};
struct GDescs4 { GDesc d[4]; };

// ------------------------------ fused GEMM ---------------------------------
// C[256,N] = A[256,K] @ B[K,N]; per-output strictly-ascending-k FFMA chain.
// BM=128 x BN=64 tile (round-13 proven), 256 threads, TM=8 x TN=4 per thread:
// ~75 regs -> 3 blocks/SM resident (24 warps/SM) to hide LDS/sync latency.
__global__ void __launch_bounds__(NTHREADS, 2)
fused_gemm(GDescs4 descs) {
    const GDesc d = descs.d[blockIdx.z];
    if ((int)blockIdx.y * BN >= d.N) return;

    __shared__ float As[2][BK][BM + 4];
    __shared__ float Bs[2][BK][BN];

    const int tid = threadIdx.x;
    const int tx = tid & 15;       // 16 col-groups * TN=4 -> 64 cols
    const int ty = tid >> 4;       // 16 row-groups * TM=8 -> 128 rows
    const int m0 = blockIdx.x * BM;
    const int n0 = blockIdx.y * BN;

    float acc[TM][TN];
#pragma unroll
    for (int i = 0; i < TM; i++)
#pragma unroll
        for (int j = 0; j < TN; j++) acc[i][j] = 0.f;

    const int total = (d.K + BK - 1) / BK;

    float aReg[8];                 // 128*16/256 = 8 A elems per thread
    float4 bReg;                   // 16*64/256  = 4 B elems = 1 float4

    auto g2r = [&](int t) {
        const int k0 = t * BK;
#pragma unroll
        for (int i = 0; i < 8; i++) {
            int e = tid + i * NTHREADS;       // 128*16 = 2048 elems
            int m = e >> 4, k = e & 15;
            int kg = k0 + k;
            aReg[i] = (kg < d.K) ? d.A[(m0 + m) * d.K + kg] : 0.f;
        }
        {
            int r = tid >> 4, c4 = tid & 15;  // 16 rows x 16 float4
            int kg = k0 + r;
            bReg = (kg < d.K) ? *(const float4*)(d.B + (ll)kg * d.N + n0 + c4 * 4)
                              : make_float4(0.f, 0.f, 0.f, 0.f);
        }
    };
    auto r2s = [&](int buf) {
#pragma unroll
        for (int i = 0; i < 8; i++) {
            int e = tid + i * NTHREADS;
            As[buf][e & 15][e >> 4] = aReg[i];
        }
        *(float4*)&Bs[buf][tid >> 4][(tid & 15) * 4] = bReg;
    };

    g2r(0); r2s(0); __syncthreads();

    for (int t = 0; t < total; ++t) {
        const int cur = t & 1;
        if (t + 1 < total) g2r(t + 1);
#pragma unroll
        for (int k = 0; k < BK; k++) {       // ascending k: single FFMA chain per output
            float a[TM], b[TN];
            *(float4*)&a[0] = *(const float4*)&As[cur][k][ty * TM];
            *(float4*)&a[4] = *(const float4*)&As[cur][k][ty * TM + 4];
            *(float4*)&b[0] = *(const float4*)&Bs[cur][k][tx * TN];
#pragma unroll
            for (int i = 0; i < TM; i++)
#pragma unroll
                for (int j = 0; j < TN; j++)
                    acc[i][j] += a[i] * b[j];   // FFMA (zero-padded terms exact no-ops)
        }
        if (t + 1 < total) r2s(cur ^ 1);
        __syncthreads();
    }

    // epilogue — exact separate-rounded ops in reference order
#pragma unroll
    for (int i = 0; i < TM; i++) {
        const int row = m0 + ty * TM + i;
#pragma unroll
        for (int j = 0; j < TN; j++) {
            const int col = n0 + tx * TN + j;
            const int idx = row * d.N + col;
            float G = acc[i][j];
            if (d.mode == 11) { d.e_out[idx] = G; continue; }
            if (d.mode == 12) {
                float t0 = __fadd_rn(-d.bias1[idx], -d.bias2[idx]);  // (-ed) + (-eg)
                d.e_out[idx] = __fadd_rn(t0, G);                     // (..) + G1
                continue;
            }
            if (d.mode == 10) {
                d.e_out[idx] = __fmul_rn(0.5f, __fsub_rn(d.e_ref[idx], G));
                continue;
            }
            float inp = (d.mode == 0) ? G : __fadd_rn(d.bias1[idx], G);  // P + G2
            float jm = d.jm[idx], v = d.v[idx], s;
            lif_ref(inp, v, jm, s);
            d.jm[idx] = jm; d.v[idx] = v;
            if (d.mode == 0) {
                d.e_out[idx] = __fmul_rn(0.5f, __fsub_rn(d.e_ref[idx], s));  // eg0
            } else {
                d.sp[idx] = s;
                float x = d.xt[idx];
                float q = __fdiv_rn(x, 20.0f);
                x = __fadd_rn(x, __fadd_rn(s, -q));   // x + ((-x/20) + s)
                d.xt[idx] = x;
                if (d.e_out)
                    d.e_out[idx] = __fmul_rn(0.5f, __fsub_rn(x, d.e_ref[idx]));
            }
        }
    }
}

// --------- label layer: one thread per output, ascending-k FMA chain --------
__global__ void label_k(const float* __restrict__ s3, const float* __restrict__ V3,
                        const float* __restrict__ y,
                        float* v4, float* j4, float* ed4, float* sc, float* vs) {
    int idx = blockIdx.x * blockDim.x + threadIdx.x;    // BATCH*DL = 2560
    if (idx >= BATCH * DL) return;
    int b = idx / DL, n = idx % DL;
    const float* srow = s3 + (ll)b * DH;
    const float* vrow = V3 + (ll)n * DH;                // V3 [DL][DH]: row n
    float acc = 0.f;
    for (int k = 0; k < DH; k++)
        acc += srow[k] * vrow[k];                       // single FFMA chain
    float jm = j4[idx], v = v4[idx], s;
    lif_ref(acc, v, jm, s);
    j4[idx] = jm; v4[idx] = v;
    ed4[idx] = __fmul_rn(0.5f, __fsub_rn(y[idx], s));
    sc[idx] = __fadd_rn(sc[idx], s);
    vs[idx] = __fadd_rn(vs[idx], v);
}

// ------------------------------ helpers ------------------------------------
struct TDesc { const float* src; float* dst; int rows, cols; };
struct TDescs { TDesc d[6]; };

__global__ void transpose_k(TDescs ds) {
    TDesc d = ds.d[blockIdx.z];
    const int c0 = blockIdx.x * 32, r0 = blockIdx.y * 32;
    if (c0 >= d.cols || r0 >= d.rows) return;
    __shared__ float tile[32][33];
    const int tx = threadIdx.x, ty = threadIdx.y;   // 32x8
    for (int i = ty; i < 32; i += 8) {
        int r = r0 + i, c = c0 + tx;
        tile[i][tx] = (r < d.rows && c < d.cols) ? d.src[(ll)r * d.cols + c] : 0.f;
    }
    __syncthreads();
    for (int i = ty; i < 32; i += 8) {
        int c = c0 + i, r = r0 + tx;
        if (c < d.cols && r < d.rows) d.dst[(ll)c * d.rows + r] = tile[tx][i];
    }
}

__global__ void ygemm_k(const float* __restrict__ y, const float* __restrict__ W3,
                        float* __restrict__ out) {
    int idx = blockIdx.x * blockDim.x + threadIdx.x;     // BATCH*DH
    if (idx >= BATCH * DH) return;
    int b = idx / DH, n = idx % DH;
    float acc = 0.f;
#pragma unroll
    for (int k = 0; k < DL; k++)
        acc += y[b * DL + k] * W3[(ll)n * DL + k];       // ascending FFMA chain
    out[idx] = acc;
}

__global__ void zero_k(float* p, ll n) {
    ll i = (ll)blockIdx.x * blockDim.x + threadIdx.x;
    if (i < n) p[i] = 0.f;
}

__global__ void writeout_k(const float* sc, const float* vs, float* out) {
    int i = blockIdx.x * blockDim.x + threadIdx.x;
    if (i < BATCH * DL) out[i] = sc[i];
    else if (i < 2 * BATCH * DL) out[i] = vs[i - BATCH * DL];
}

// ------------------------------ host side ----------------------------------
static inline GDesc mk(const float* A, const float* B, int K, int N, int mode,
                       float* v, float* jm, float* sp, float* xt,
                       const float* b1, const float* b2,
                       float* e_out, const float* e_ref) {
    GDesc g; g.A = A; g.B = B; g.K = K; g.N = N; g.mode = mode;
    g.v = v; g.jm = jm; g.sp = sp; g.xt = xt;
    g.bias1 = b1; g.bias2 = b2; g.e_out = e_out; g.e_ref = e_ref;
    return g;
}

extern "C" void kernel_launch(void* const* d_in, const int* in_sizes, int n_in,
                              void* d_out, int out_size) {
    // metadata order = setup_inputs() dict insertion order (interleaved W/V):
    const float* x_data = (const float*)d_in[0];
    const float* y_t    = (const float*)d_in[1];
    const float* W0 = (const float*)d_in[2];   // [1024][2048]
    const float* V0 = (const float*)d_in[3];   // [2048][1024]
    const float* W1 = (const float*)d_in[4];   // [2048][2048]
    const float* V1 = (const float*)d_in[5];   // [2048][2048]
    const float* W2 = (const float*)d_in[6];   // [2048][2048]
    const float* V2 = (const float*)d_in[7];   // [2048][2048]
    const float* W3 = (const float*)d_in[8];   // [2048][10]
    const float* V3 = (const float*)d_in[9];   // [10][2048]
    float* out = (float*)d_out;

    float* buf = nullptr;
    cudaGetSymbolAddress((void**)&buf, g_buf);

    // zero mutable state
    {
        ll nz = O_END - O_STATE;
        zero_k<<<(unsigned)((nz + 255) / 256), 256>>>(buf + O_STATE, nz);
    }

    // one-time weight transposes
    {
        TDescs td;
        td.d[0] = { W0, buf + O_W0T, D0, DH };
        td.d[1] = { W1, buf + O_W1T, DH, DH };
        td.d[2] = { W2, buf + O_W2T, DH, DH };
        td.d[3] = { V0, buf + O_V0T, DH, D0 };
        td.d[4] = { V1, buf + O_V1T, DH, DH };
        td.d[5] = { V2, buf + O_V2T, DH, DH };
        transpose_k<<<dim3(64, 64, 6), dim3(32, 8)>>>(td);
    }

    // loop-invariant GEMMs
    ygemm_k<<<(BATCH * DH + 255) / 256, 256>>>(y_t, W3, buf + O_YW3);
    {
        GDescs4 g;
        g.d[0] = mk(x_data, buf + O_V0T, D0, DH, 11,
                    nullptr, nullptr, nullptr, nullptr, nullptr, nullptr,
                    buf + O_XDV, nullptr);
        g.d[1] = g.d[0]; g.d[2] = g.d[0]; g.d[3] = g.d[0];
        fused_gemm<<<dim3(BATCH / BM, 32, 1), NTHREADS>>>(g);
    }

    for (int t = 0; t < TSTEPS; ++t) {
        const int cur = t & 1;
        float* eg0c = buf + (cur ? O_EG0B : O_EG0A);
        float* eg0p = buf + (cur ? O_EG0A : O_EG0B);
        float* s1c  = buf + (cur ? O_S1B : O_S1A);
        float* s1p  = buf + (cur ? O_S1A : O_S1B);

        // ---- update pass 1: layer0 LIF + partials P_i = (-ed_i - eg_i) + G1_i ----
        GDescs4 u1;
        u1.d[0] = mk(s1p, buf + O_W0T, DH, D0, 0,
                     buf + O_V0L, buf + O_J0, nullptr, nullptr,
                     nullptr, nullptr, eg0c, x_data);
        u1.d[1] = mk(eg0p, W0, D0, DH, 12,
                     nullptr, nullptr, nullptr, nullptr,
                     buf + O_ED1, buf + O_EG1, buf + O_P1, nullptr);
        u1.d[2] = mk(buf + O_EG1, W1, DH, DH, 12,
                     nullptr, nullptr, nullptr, nullptr,
                     buf + O_ED2, buf + O_EG2, buf + O_P2, nullptr);
        u1.d[3] = mk(buf + O_EG2, W2, DH, DH, 12,
                     nullptr, nullptr, nullptr, nullptr,
                     buf + O_ED3, buf + O_EG3, buf + O_P3, nullptr);
        fused_gemm<<<dim3(BATCH / BM, 32, 4), NTHREADS>>>(u1);

        // ---- update pass 2: inp_i = P_i + G2_i, LIF + trace (+ fused ed1/eg3) ----
        GDescs4 u2;
        u2.d[0] = mk(buf + O_ED2, V1, DH, DH, 1,
                     buf + O_V1, buf + O_J1, s1c, buf + O_X1,
                     buf + O_P1, nullptr, buf + O_ED1, buf + O_XDV);
        u2.d[1] = mk(buf + O_ED3, V2, DH, DH, 1,
                     buf + O_V2, buf + O_J2, buf + O_S2, buf + O_X2,
                     buf + O_P2, nullptr, nullptr, nullptr);
        u2.d[2] = mk(buf + O_ED4, V3, DL, DH, 1,
                     buf + O_V3L, buf + O_J3, buf + O_S3, buf + O_X3,
                     buf + O_P3, nullptr, buf + O_EG3, buf + O_YW3);
        u2.d[3] = u2.d[2];   // unused (grid.z = 3)
        fused_gemm<<<dim3(BATCH / BM, 32, 3), NTHREADS>>>(u2);

        // ---- label layer (fresh s3) + readout accumulation ----
        label_k<<<(BATCH * DL + 255) / 256, 256>>>(buf + O_S3, V3, y_t,
                                                   buf + O_V4, buf + O_J4, buf + O_ED4,
                                                   buf + O_SC, buf + O_VS);

        // ---- error phase: 4 single-chain GEMMs ----
        GDescs4 e;
        e.d[0] = mk(buf + O_S2, buf + O_W1T, DH, DH, 10,
                    nullptr, nullptr, nullptr, nullptr, nullptr, nullptr,
                    buf + O_EG1, buf + O_X1);   // eg1 = .5(x1 - s2@W1^T)
        e.d[1] = mk(s1c, buf + O_V1T, DH, DH, 10,
                    nullptr, nullptr, nullptr, nullptr, nullptr, nullptr,
                    buf + O_ED2, buf + O_X2);   // ed2 = .5(x2 - s1@V1^T)
        e.d[2] = mk(buf + O_S3, buf + O_W2T, DH, DH, 10,
                    nullptr, nullptr, nullptr, nullptr, nullptr, nullptr,
                    buf + O_EG2, buf + O_X2);   // eg2 = .5(x2 - s3@W2^T)
        e.d[3] = mk(buf + O_S2, buf + O_V2T, DH, DH, 10,
                    nullptr, nullptr, nullptr, nullptr, nullptr, nullptr,
                    buf + O_ED3, buf + O_X3);   // ed3 = .5(x3 - s2@V2^T)
        fused_gemm<<<dim3(BATCH / BM, 32, 4), NTHREADS>>>(e);
    }

    writeout_k<<<(2 * BATCH * DL + 255) / 256, 256>>>(buf + O_SC, buf + O_VS, out);
}